// round 9
// baseline (speedup 1.0000x reference)
#include <cuda_runtime.h>
#include <math.h>
#include <stdint.h>

#define BB 128
#define TT 512
#define DD 1024
#define HH 1024
#define NGATE 4096   // 4*H
#define NCTA 256     // persistent grid size (2/SM, all co-resident)

#define LDB 136      // xgates B smem row stride (words): 136 % 32 == 8 -> conflict-free
#define LDBR 72      // recurrence B smem row stride (64n + 8 pad): 72 % 32 == 8 -> conflict-free
#define LDAK 36      // A smem row stride (words, [m][k] layout): 36 % 32 == 4 -> conflict-free

// Scratch (static device globals — no runtime allocation).
__device__ float g_xg[(size_t)TT * BB * NGATE];        // [t][b][4H] input projections
__device__ float g_part[4 * BB * NGATE];               // split-K partials [ks][b][4H]
__device__ float g_h[BB * HH];                         // recurrent h
__device__ unsigned g_bar;                             // grid barrier counter (never reset)

__device__ __forceinline__ uint32_t f2tf32(float f)
{
    uint32_t u;
    asm("cvt.rna.tf32.f32 %0, %1;" : "=r"(u) : "f"(f));
    return u;
}

__device__ __forceinline__ void mma_tf32(float* d, const uint32_t* a, const uint32_t* b)
{
    asm volatile(
        "mma.sync.aligned.m16n8k8.row.col.f32.tf32.tf32.f32 "
        "{%0,%1,%2,%3},{%4,%5,%6,%7},{%8,%9},{%0,%1,%2,%3};"
        : "+f"(d[0]), "+f"(d[1]), "+f"(d[2]), "+f"(d[3])
        : "r"(a[0]), "r"(a[1]), "r"(a[2]), "r"(a[3]), "r"(b[0]), "r"(b[1]));
}

__device__ __forceinline__ void cpa16(uint32_t dst_smem, const void* src)
{
    asm volatile("cp.async.cg.shared.global [%0], [%1], 16;"
                 :: "r"(dst_smem), "l"(src));
}
__device__ __forceinline__ void cpa_commit()
{
    asm volatile("cp.async.commit_group;");
}
template <int N> __device__ __forceinline__ void cpa_wait()
{
    asm volatile("cp.async.wait_group %0;" :: "n"(N));
}

extern __shared__ float dynf[];

// ---------------------------------------------------------------------------
// GEMM1 (tf32): xg[t][b][n] = sum_k x[b][t][k] * Wx[g][k][h]  — R8 version.
// 3-stage cp.async pipeline; tf32 conversion at fragment read.
// ---------------------------------------------------------------------------
#define XGA (128 * LDAK)        // 4608 words per A stage
#define XGB (32 * LDB)          // 4352 words per B stage

__global__ __launch_bounds__(256, 2) void gemm_xgates(
    const float* __restrict__ x, const float* __restrict__ Wx,
    float* __restrict__ out)
{
    float* Sa = dynf;                 // [3][128][LDAK]
    float* Sb = dynf + 3 * XGA;       // [3][32][LDB]
    const uint32_t sa_base = (uint32_t)__cvta_generic_to_shared(Sa);
    const uint32_t sb_base = (uint32_t)__cvta_generic_to_shared(Sb);

    const int tid  = threadIdx.x;
    const int lane = tid & 31;
    const int wid  = tid >> 5;
    const int gq   = lane >> 2;
    const int cq   = lane & 3;

    const int t  = blockIdx.y;
    const int n0 = blockIdx.x * 128;
    const int gg = n0 >> 10;
    const int hb = n0 & 1023;

    const int m0w = (wid >> 2) * 64;
    const int n0w = (wid & 3) * 32;

    float acc[4][4][4];
#pragma unroll
    for (int i = 0; i < 4; i++)
#pragma unroll
        for (int j = 0; j < 4; j++)
#pragma unroll
            for (int e = 0; e < 4; e++) acc[i][j][e] = 0.f;

    const float* Wg = Wx + (size_t)gg * DD * HH + hb;

    const int am  = tid >> 1;
    const int asg = (tid & 1) * 4;
    const float* axsrc = x + (size_t)am * (TT * DD) + (size_t)t * DD + asg * 4;
    const int bk  = tid >> 3;
    const int bsg = (tid & 7) * 4;

    auto copy_stage = [&](int kt) {
        int s = kt % 3;
        uint32_t da = sa_base + (uint32_t)(s * XGA + am * LDAK + asg * 4) * 4;
        const float* srca = axsrc + kt * 32;
#pragma unroll
        for (int j = 0; j < 4; j++)
            cpa16(da + j * 16, srca + j * 4);
        uint32_t db = sb_base + (uint32_t)(s * XGB + bk * LDB + bsg * 4) * 4;
        const float* srcb = Wg + (size_t)(kt * 32 + bk) * HH + bsg * 4;
#pragma unroll
        for (int j = 0; j < 4; j++)
            cpa16(db + j * 16, srcb + j * 4);
        cpa_commit();
    };

    copy_stage(0);
    copy_stage(1);

    for (int kt = 0; kt < 32; kt++) {
        if (kt == 31) cpa_wait<0>(); else cpa_wait<1>();
        __syncthreads();
        if (kt + 2 < 32) copy_stage(kt + 2);

        const float* Af = Sa + (kt % 3) * XGA;
        const float* Bf = Sb + (kt % 3) * XGB;
#pragma unroll
        for (int kk = 0; kk < 4; kk++) {
            const int kb = kk * 8;
            uint32_t af[4][4], bf[4][2];
#pragma unroll
            for (int mt = 0; mt < 4; mt++) {
                int m = m0w + mt * 16 + gq;
                af[mt][0] = f2tf32(Af[m * LDAK + kb + cq]);
                af[mt][1] = f2tf32(Af[(m + 8) * LDAK + kb + cq]);
                af[mt][2] = f2tf32(Af[m * LDAK + kb + cq + 4]);
                af[mt][3] = f2tf32(Af[(m + 8) * LDAK + kb + cq + 4]);
            }
#pragma unroll
            for (int nt = 0; nt < 4; nt++) {
                int n = n0w + nt * 8 + gq;
                bf[nt][0] = f2tf32(Bf[(kb + cq) * LDB + n]);
                bf[nt][1] = f2tf32(Bf[(kb + cq + 4) * LDB + n]);
            }
#pragma unroll
            for (int mt = 0; mt < 4; mt++)
#pragma unroll
                for (int nt = 0; nt < 4; nt++)
                    mma_tf32(acc[mt][nt], af[mt], bf[nt]);
        }
    }

#pragma unroll
    for (int mt = 0; mt < 4; mt++) {
        int r0 = m0w + mt * 16 + gq;
#pragma unroll
        for (int nt = 0; nt < 4; nt++) {
            int cc = n0 + n0w + nt * 8 + 2 * cq;
            float* p0 = out + ((size_t)t * BB + r0) * NGATE + cc;
            float* p1 = out + ((size_t)t * BB + r0 + 8) * NGATE + cc;
            *(float2*)p0 = make_float2(acc[mt][nt][0], acc[mt][nt][1]);
            *(float2*)p1 = make_float2(acc[mt][nt][2], acc[mt][nt][3]);
        }
    }
}

// ---------------------------------------------------------------------------
// Grid barrier: arrive via atomic; tight volatile spin (no nanosleep).
// ---------------------------------------------------------------------------
__device__ __forceinline__ void grid_barrier()
{
    __syncthreads();
    if (threadIdx.x == 0) {
        __threadfence();
        unsigned old = atomicAdd(&g_bar, 1u);
        unsigned target = (old / NCTA + 1u) * (unsigned)NCTA;
        while (*(volatile unsigned*)&g_bar < target) { }
        __threadfence();
    }
    __syncthreads();
}

// ---------------------------------------------------------------------------
// Persistent recurrence (tf32): 256 CTAs (2/SM) x 256 threads, 512 steps.
// CTA = (n-tile 0..63 width 64, k-split 0..3). Wh slice (256k x 64n, tf32,
// stride 72) persists in smem; h streams per step in 8 chunks of k32 via
// 2-stage cp.async ring ([m][36] raw f32, cvt at read). Warp grid 4m x 2n,
// warp tile 32x32. Activation: CTA owns half of batch row bx>>1, c in regs.
// ---------------------------------------------------------------------------
#define RCA (128 * LDAK)   // words per A ring stage

__global__ __launch_bounds__(256, 2) void lstm_recurrence(
    const float* __restrict__ Wh, const float* __restrict__ xg,
    const float* __restrict__ bias, float* __restrict__ out)
{
    uint32_t* BsW = (uint32_t*)dynf;            // [256][LDBR] persistent Wh (tf32 bits)
    float* Aring  = dynf + 256 * LDBR;          // [2][128][LDAK] raw f32 h chunks
    const uint32_t ar_base = (uint32_t)__cvta_generic_to_shared(Aring);

    const int tid  = threadIdx.x;
    const int lane = tid & 31;
    const int wid  = tid >> 5;
    const int gq   = lane >> 2;
    const int cq   = lane & 3;

    const int nt = blockIdx.x & 63;     // n-tile (width 64)
    const int ks = blockIdx.x >> 6;     // k-split 0..3
    const int n0 = nt * 64;
    const int gg = n0 >> 10;
    const int hb = n0 & 1023;
    const int k0 = ks * 256;

    const int m0w = (wid >> 1) * 32;    // 4 warps along m
    const int n0w = (wid & 1) * 32;     // 2 warps along n

    const float* Wg = Wh + (size_t)gg * HH * HH + hb;

    // ---- preload Wh slice -> BsW[k][n] (tf32, stride 72), once ----
    for (int i = tid; i < 256 * 16; i += 256) {   // float4 granules: 256k x 16
        int kr = i >> 4;
        int nc = (i & 15) * 4;
        float4 v = *(const float4*)(Wg + (size_t)(k0 + kr) * HH + nc);
        BsW[kr * LDBR + nc + 0] = f2tf32(v.x);
        BsW[kr * LDBR + nc + 1] = f2tf32(v.y);
        BsW[kr * LDBR + nc + 2] = f2tf32(v.z);
        BsW[kr * LDBR + nc + 3] = f2tf32(v.w);
    }

    // Activation role: row bown = bx>>1, cols hc2 = (bx&1)*512 + tid*2
    const int bown = blockIdx.x >> 1;
    const int hc2  = (blockIdx.x & 1) * 512 + tid * 2;
    float2 creg = make_float2(0.f, 0.f);
    float2 bb0 = *(const float2*)(bias + hc2);
    float2 bb1 = *(const float2*)(bias + 1024 + hc2);
    float2 bb2 = *(const float2*)(bias + 2048 + hc2);
    float2 bb3 = *(const float2*)(bias + 3072 + hc2);

    *(float2*)(g_h + bown * HH + hc2) = make_float2(0.f, 0.f);
    grid_barrier();

    // A copy mapping: row m = tid>>1, segs (tid&1)*4 + j of 8 per row
    const int am  = tid >> 1;
    const int asg = (tid & 1) * 4;
    const float* hsrc = g_h + (size_t)am * HH + k0 + asg * 4;

    for (int t = 0; t < TT; t++) {
        float acc[2][4][4];
#pragma unroll
        for (int i = 0; i < 2; i++)
#pragma unroll
            for (int j = 0; j < 4; j++)
#pragma unroll
                for (int e = 0; e < 4; e++) acc[i][j][e] = 0.f;

        auto copy_chunk = [&](int c) {
            uint32_t da = ar_base + (uint32_t)((c & 1) * RCA + am * LDAK + asg * 4) * 4;
            const float* src = hsrc + c * 32;
#pragma unroll
            for (int j = 0; j < 4; j++)
                cpa16(da + j * 16, src + j * 4);
            cpa_commit();
        };

        copy_chunk(0);

#pragma unroll
        for (int c = 0; c < 8; c++) {
            cpa_wait<0>();
            __syncthreads();
            if (c + 1 < 8) copy_chunk(c + 1);

            const float* Af = Aring + (c & 1) * RCA;
#pragma unroll
            for (int kk = 0; kk < 4; kk++) {
                const int kb = kk * 8;
                const int kw = c * 32 + kb;
                uint32_t af[2][4], bf[4][2];
#pragma unroll
                for (int mt = 0; mt < 2; mt++) {
                    int m = m0w + mt * 16 + gq;
                    af[mt][0] = f2tf32(Af[m * LDAK + kb + cq]);
                    af[mt][1] = f2tf32(Af[(m + 8) * LDAK + kb + cq]);
                    af[mt][2] = f2tf32(Af[m * LDAK + kb + cq + 4]);
                    af[mt][3] = f2tf32(Af[(m + 8) * LDAK + kb + cq + 4]);
                }
#pragma unroll
                for (int nt2 = 0; nt2 < 4; nt2++) {
                    int n = n0w + nt2 * 8 + gq;
                    bf[nt2][0] = BsW[(kw + cq) * LDBR + n];
                    bf[nt2][1] = BsW[(kw + cq + 4) * LDBR + n];
                }
#pragma unroll
                for (int mt = 0; mt < 2; mt++)
#pragma unroll
                    for (int nt2 = 0; nt2 < 4; nt2++)
                        mma_tf32(acc[mt][nt2], af[mt], bf[nt2]);
            }
        }

        // store partials
        float* pbase = g_part + (size_t)ks * (BB * NGATE);
#pragma unroll
        for (int mt = 0; mt < 2; mt++) {
            int r0 = m0w + mt * 16 + gq;
#pragma unroll
            for (int nt2 = 0; nt2 < 4; nt2++) {
                int cc = n0 + n0w + nt2 * 8 + 2 * cq;
                *(float2*)(pbase + (size_t)r0 * NGATE + cc) =
                    make_float2(acc[mt][nt2][0], acc[mt][nt2][1]);
                *(float2*)(pbase + (size_t)(r0 + 8) * NGATE + cc) =
                    make_float2(acc[mt][nt2][2], acc[mt][nt2][3]);
            }
        }

        grid_barrier();   // partials visible

        // ---- fused activation (half row per CTA) ----
        {
            const float* xgb = xg + ((size_t)t * BB + bown) * NGATE;
            const float* p0 = g_part + (size_t)bown * NGATE;
            const float* p1 = p0 + 1 * (size_t)(BB * NGATE);
            const float* p2 = p0 + 2 * (size_t)(BB * NGATE);
            const float* p3 = p0 + 3 * (size_t)(BB * NGATE);

            float gv[4][2];
#pragma unroll
            for (int gi = 0; gi < 4; gi++) {
                int n = (gi << 10) | hc2;
                float2 v  = *(const float2*)(xgb + n);
                float2 q0 = *(const float2*)(p0 + n);
                float2 q1 = *(const float2*)(p1 + n);
                float2 q2 = *(const float2*)(p2 + n);
                float2 q3 = *(const float2*)(p3 + n);
                gv[gi][0] = v.x + q0.x + q1.x + q2.x + q3.x;
                gv[gi][1] = v.y + q0.y + q1.y + q2.y + q3.y;
            }
            gv[0][0] += bb0.x; gv[0][1] += bb0.y;
            gv[1][0] += bb1.x; gv[1][1] += bb1.y;
            gv[2][0] += bb2.x; gv[2][1] += bb2.y;
            gv[3][0] += bb3.x; gv[3][1] += bb3.y;

            float hv[2];
            float* cr = (float*)&creg;
#pragma unroll
            for (int e = 0; e < 2; e++) {
                float ig = 1.f / (1.f + expf(-gv[0][e]));
                float fg = 1.f / (1.f + expf(-gv[1][e]));
                float og = 1.f / (1.f + expf(-gv[2][e]));
                float ug = tanhf(gv[3][e]);
                float c = fg * cr[e] + ig * ug;
                cr[e] = c;
                hv[e] = og * tanhf(c);
            }
            float2 hvec = make_float2(hv[0], hv[1]);
            if (t == TT - 1)
                *(float2*)(out + bown * HH + hc2) = hvec;
            else
                *(float2*)(g_h + bown * HH + hc2) = hvec;
        }

        grid_barrier();   // h visible before next GEMM
    }
}

// ---------------------------------------------------------------------------
// Launch. Inputs: x[128,512,1024], adjacency (unused), Wx[4,1024,1024],
// Wh[4,1024,1024], b[4,1024]. Output: h [128,1024] f32. Graph: 2 nodes.
// ---------------------------------------------------------------------------
extern "C" void kernel_launch(void* const* d_in, const int* in_sizes, int n_in,
                              void* d_out, int out_size)
{
    const float* x    = (const float*)d_in[0];
    const float* Wx   = (const float*)d_in[2];
    const float* Wh   = (const float*)d_in[3];
    const float* bias = (const float*)d_in[4];
    float* out = (float*)d_out;

    float* xg;
    cudaGetSymbolAddress((void**)&xg, g_xg);

    const int xg_smem  = (3 * XGA + 3 * XGB) * 4;           // 107520 B (2 CTAs/SM)
    const int rec_smem = (256 * LDBR + 2 * RCA) * 4;        // 110592 B (2 CTAs/SM)
    static int configured = 0;
    if (!configured) {
        cudaFuncSetAttribute(gemm_xgates,
                             cudaFuncAttributeMaxDynamicSharedMemorySize, xg_smem);
        cudaFuncSetAttribute(lstm_recurrence,
                             cudaFuncAttributeMaxDynamicSharedMemorySize, rec_smem);
        configured = 1;
    }

    gemm_xgates<<<dim3(32, 512), 256, xg_smem>>>(x, Wx, xg);
    lstm_recurrence<<<NCTA, 256, rec_smem>>>(Wh, xg, bias, out);
}

// round 10
// speedup vs baseline: 1.1970x; 1.1970x over previous
#include <cuda_runtime.h>
#include <math.h>
#include <stdint.h>

#define BB 128
#define TT 512
#define DD 1024
#define HH 1024
#define NGATE 4096   // 4*H
#define NCTA 128     // persistent grid size (1/SM, all co-resident)

#define LDB 136      // B smem row stride (words): 136 % 32 == 8 -> conflict-free
#define LDAK 36      // A smem row stride (words, [m][k] layout): 36 % 32 == 4 -> conflict-free

// Scratch (static device globals — no runtime allocation).
__device__ float g_xg[(size_t)TT * BB * NGATE];        // [t][b][4H] input projections
__device__ float g_part[4 * BB * NGATE];               // split-K partials [ks][b][4H]
__device__ float g_h[BB * HH];                         // recurrent h
__device__ unsigned g_bar;                             // grid barrier counter (never reset)

__device__ __forceinline__ uint32_t f2tf32(float f)
{
    uint32_t u;
    asm("cvt.rna.tf32.f32 %0, %1;" : "=r"(u) : "f"(f));
    return u;
}

__device__ __forceinline__ void mma_tf32(float* d, const uint32_t* a, const uint32_t* b)
{
    asm volatile(
        "mma.sync.aligned.m16n8k8.row.col.f32.tf32.tf32.f32 "
        "{%0,%1,%2,%3},{%4,%5,%6,%7},{%8,%9},{%0,%1,%2,%3};"
        : "+f"(d[0]), "+f"(d[1]), "+f"(d[2]), "+f"(d[3])
        : "r"(a[0]), "r"(a[1]), "r"(a[2]), "r"(a[3]), "r"(b[0]), "r"(b[1]));
}

__device__ __forceinline__ void cpa16(uint32_t dst_smem, const void* src)
{
    asm volatile("cp.async.cg.shared.global [%0], [%1], 16;"
                 :: "r"(dst_smem), "l"(src));
}
__device__ __forceinline__ void cpa_commit()
{
    asm volatile("cp.async.commit_group;");
}
template <int N> __device__ __forceinline__ void cpa_wait()
{
    asm volatile("cp.async.wait_group %0;" :: "n"(N));
}

extern __shared__ float dynf[];

// ---------------------------------------------------------------------------
// GEMM1 (tf32): xg[t][b][n] = sum_k x[b][t][k] * Wx[g][k][h]
// 512 threads (16 warps, 4/SMSP), block tile 128x128x32, warp grid 4m x 4n,
// warp tile 32x32. 3-stage cp.async pipeline; tf32 cvt at fragment read.
// ---------------------------------------------------------------------------
#define XGA (128 * LDAK)        // 4608 words per A stage
#define XGB (32 * LDB)          // 4352 words per B stage

__global__ __launch_bounds__(512, 1) void gemm_xgates(
    const float* __restrict__ x, const float* __restrict__ Wx,
    float* __restrict__ out)
{
    float* Sa = dynf;                 // [3][128][LDAK]
    float* Sb = dynf + 3 * XGA;       // [3][32][LDB]
    const uint32_t sa_base = (uint32_t)__cvta_generic_to_shared(Sa);
    const uint32_t sb_base = (uint32_t)__cvta_generic_to_shared(Sb);

    const int tid  = threadIdx.x;
    const int lane = tid & 31;
    const int wid  = tid >> 5;        // 0..15
    const int gq   = lane >> 2;
    const int cq   = lane & 3;

    const int t  = blockIdx.y;
    const int n0 = blockIdx.x * 128;
    const int gg = n0 >> 10;
    const int hb = n0 & 1023;

    const int m0w = (wid >> 2) * 32;  // 4 warps along m
    const int n0w = (wid & 3) * 32;   // 4 warps along n

    float acc[2][4][4];
#pragma unroll
    for (int i = 0; i < 2; i++)
#pragma unroll
        for (int j = 0; j < 4; j++)
#pragma unroll
            for (int e = 0; e < 4; e++) acc[i][j][e] = 0.f;

    const float* Wg = Wx + (size_t)gg * DD * HH + hb;

    // A copy: row am = tid>>2 (0..127), segs (tid&3)*2 + j (8 x 16B per row)
    const int am  = tid >> 2;
    const int as0 = (tid & 3) * 2;
    const float* axsrc = x + (size_t)am * (TT * DD) + (size_t)t * DD + as0 * 4;
    // B copy: row bk = tid>>4 (0..31), segs (tid&15)*2 + j (32 x 16B per row)
    const int bk  = tid >> 4;
    const int bs0 = (tid & 15) * 2;

    auto copy_stage = [&](int kt) {
        int s = kt % 3;
        uint32_t da = sa_base + (uint32_t)(s * XGA + am * LDAK + as0 * 4) * 4;
        const float* srca = axsrc + kt * 32;
#pragma unroll
        for (int j = 0; j < 2; j++)
            cpa16(da + j * 16, srca + j * 4);
        uint32_t db = sb_base + (uint32_t)(s * XGB + bk * LDB + bs0 * 4) * 4;
        const float* srcb = Wg + (size_t)(kt * 32 + bk) * HH + bs0 * 4;
#pragma unroll
        for (int j = 0; j < 2; j++)
            cpa16(db + j * 16, srcb + j * 4);
        cpa_commit();
    };

    copy_stage(0);
    copy_stage(1);

    for (int kt = 0; kt < 32; kt++) {
        if (kt == 31) cpa_wait<0>(); else cpa_wait<1>();
        __syncthreads();
        if (kt + 2 < 32) copy_stage(kt + 2);

        const float* Af = Sa + (kt % 3) * XGA;
        const float* Bf = Sb + (kt % 3) * XGB;
#pragma unroll
        for (int kk = 0; kk < 4; kk++) {
            const int kb = kk * 8;
            uint32_t af[2][4], bf[4][2];
#pragma unroll
            for (int mt = 0; mt < 2; mt++) {
                int m = m0w + mt * 16 + gq;
                af[mt][0] = f2tf32(Af[m * LDAK + kb + cq]);
                af[mt][1] = f2tf32(Af[(m + 8) * LDAK + kb + cq]);
                af[mt][2] = f2tf32(Af[m * LDAK + kb + cq + 4]);
                af[mt][3] = f2tf32(Af[(m + 8) * LDAK + kb + cq + 4]);
            }
#pragma unroll
            for (int nt = 0; nt < 4; nt++) {
                int n = n0w + nt * 8 + gq;
                bf[nt][0] = f2tf32(Bf[(kb + cq) * LDB + n]);
                bf[nt][1] = f2tf32(Bf[(kb + cq + 4) * LDB + n]);
            }
#pragma unroll
            for (int mt = 0; mt < 2; mt++)
#pragma unroll
                for (int nt = 0; nt < 4; nt++)
                    mma_tf32(acc[mt][nt], af[mt], bf[nt]);
        }
    }

#pragma unroll
    for (int mt = 0; mt < 2; mt++) {
        int r0 = m0w + mt * 16 + gq;
#pragma unroll
        for (int nt = 0; nt < 4; nt++) {
            int cc = n0 + n0w + nt * 8 + 2 * cq;
            float* p0 = out + ((size_t)t * BB + r0) * NGATE + cc;
            float* p1 = out + ((size_t)t * BB + r0 + 8) * NGATE + cc;
            *(float2*)p0 = make_float2(acc[mt][nt][0], acc[mt][nt][1]);
            *(float2*)p1 = make_float2(acc[mt][nt][2], acc[mt][nt][3]);
        }
    }
}

// ---------------------------------------------------------------------------
// Grid barrier: stateless generation counter; volatile poll + nanosleep.
// ---------------------------------------------------------------------------
__device__ __forceinline__ void grid_barrier()
{
    __syncthreads();
    if (threadIdx.x == 0) {
        __threadfence();
        unsigned old = atomicAdd(&g_bar, 1u);
        unsigned target = (old / NCTA + 1u) * (unsigned)NCTA;
        while (*(volatile unsigned*)&g_bar < target) { __nanosleep(32); }
        __threadfence();
    }
    __syncthreads();
}

// ---------------------------------------------------------------------------
// Persistent recurrence (tf32): 128 CTAs x 512 threads (16 warps, 4/SMSP).
// CTA = (n-tile 0..31 width 128, k-split 0..3). Wh slice (256k x 128n, tf32,
// [k][n] stride 136) persistent in smem; h streamed per step in 8 chunks of
// k32 via 3-stage cp.async ring ([m][36] raw f32, cvt at read). Warp grid
// 4m x 4n, warp tile 32x32. Activation: CTA b owns row b, c in registers.
// ---------------------------------------------------------------------------
#define RCA (128 * LDAK)   // words per A ring stage

__global__ __launch_bounds__(512, 1) void lstm_recurrence(
    const float* __restrict__ Wh, const float* __restrict__ xg,
    const float* __restrict__ bias, float* __restrict__ out)
{
    uint32_t* BsW = (uint32_t*)dynf;            // [256][LDB] persistent Wh (tf32 bits)
    float* Aring  = dynf + 256 * LDB;           // [3][128][LDAK] raw f32 h chunks
    const uint32_t ar_base = (uint32_t)__cvta_generic_to_shared(Aring);

    const int tid  = threadIdx.x;
    const int lane = tid & 31;
    const int wid  = tid >> 5;
    const int gq   = lane >> 2;
    const int cq   = lane & 3;

    const int nt = blockIdx.x & 31;
    const int ks = blockIdx.x >> 5;
    const int n0 = nt * 128;
    const int gg = n0 >> 10;
    const int hb = n0 & 1023;
    const int k0 = ks * 256;

    const int m0w = (wid >> 2) * 32;
    const int n0w = (wid & 3) * 32;

    const float* Wg = Wh + (size_t)gg * HH * HH + hb;

    // ---- preload Wh slice -> BsW[k][n] (tf32), once ----
    for (int i = tid; i < 256 * 32; i += 512) {   // float4 granules: 256k x 32
        int kr = i >> 5;
        int nc = (i & 31) * 4;
        float4 v = *(const float4*)(Wg + (size_t)(k0 + kr) * HH + nc);
        BsW[kr * LDB + nc + 0] = f2tf32(v.x);
        BsW[kr * LDB + nc + 1] = f2tf32(v.y);
        BsW[kr * LDB + nc + 2] = f2tf32(v.z);
        BsW[kr * LDB + nc + 3] = f2tf32(v.w);
    }

    // Activation role: batch row b = blockIdx.x, cols tid*2..+1
    const int bown = blockIdx.x;
    const int hc2  = tid * 2;
    float2 creg = make_float2(0.f, 0.f);
    float2 bb0 = *(const float2*)(bias + hc2);
    float2 bb1 = *(const float2*)(bias + 1024 + hc2);
    float2 bb2 = *(const float2*)(bias + 2048 + hc2);
    float2 bb3 = *(const float2*)(bias + 3072 + hc2);

    *(float2*)(g_h + bown * HH + hc2) = make_float2(0.f, 0.f);
    grid_barrier();

    // A copy: row am = tid>>2, segs (tid&3)*2 + j (8 x 16B per row)
    const int am  = tid >> 2;
    const int as0 = (tid & 3) * 2;
    const float* hsrc = g_h + (size_t)am * HH + k0 + as0 * 4;

    for (int t = 0; t < TT; t++) {
        float acc[2][4][4];
#pragma unroll
        for (int i = 0; i < 2; i++)
#pragma unroll
            for (int j = 0; j < 4; j++)
#pragma unroll
                for (int e = 0; e < 4; e++) acc[i][j][e] = 0.f;

        auto copy_chunk = [&](int c) {
            uint32_t da = ar_base + (uint32_t)((c % 3) * RCA + am * LDAK + as0 * 4) * 4;
            const float* src = hsrc + c * 32;
#pragma unroll
            for (int j = 0; j < 2; j++)
                cpa16(da + j * 16, src + j * 4);
            cpa_commit();
        };

        copy_chunk(0);
        copy_chunk(1);

#pragma unroll
        for (int c = 0; c < 8; c++) {
            if (c == 7) cpa_wait<0>(); else cpa_wait<1>();
            __syncthreads();
            if (c + 2 < 8) copy_chunk(c + 2);

            const float* Af = Aring + (c % 3) * RCA;
#pragma unroll
            for (int kk = 0; kk < 4; kk++) {
                const int kb = kk * 8;
                const int kw = c * 32 + kb;
                uint32_t af[2][4], bf[4][2];
#pragma unroll
                for (int mt = 0; mt < 2; mt++) {
                    int m = m0w + mt * 16 + gq;
                    af[mt][0] = f2tf32(Af[m * LDAK + kb + cq]);
                    af[mt][1] = f2tf32(Af[(m + 8) * LDAK + kb + cq]);
                    af[mt][2] = f2tf32(Af[m * LDAK + kb + cq + 4]);
                    af[mt][3] = f2tf32(Af[(m + 8) * LDAK + kb + cq + 4]);
                }
#pragma unroll
                for (int nt2 = 0; nt2 < 4; nt2++) {
                    int n = n0w + nt2 * 8 + gq;
                    bf[nt2][0] = BsW[(kw + cq) * LDB + n];
                    bf[nt2][1] = BsW[(kw + cq + 4) * LDB + n];
                }
#pragma unroll
                for (int mt = 0; mt < 2; mt++)
#pragma unroll
                    for (int nt2 = 0; nt2 < 4; nt2++)
                        mma_tf32(acc[mt][nt2], af[mt], bf[nt2]);
            }
        }

        // store partials
        float* pbase = g_part + (size_t)ks * (BB * NGATE);
#pragma unroll
        for (int mt = 0; mt < 2; mt++) {
            int r0 = m0w + mt * 16 + gq;
#pragma unroll
            for (int nt2 = 0; nt2 < 4; nt2++) {
                int cc = n0 + n0w + nt2 * 8 + 2 * cq;
                *(float2*)(pbase + (size_t)r0 * NGATE + cc) =
                    make_float2(acc[mt][nt2][0], acc[mt][nt2][1]);
                *(float2*)(pbase + (size_t)(r0 + 8) * NGATE + cc) =
                    make_float2(acc[mt][nt2][2], acc[mt][nt2][3]);
            }
        }

        grid_barrier();   // partials visible

        // ---- fused activation ----
        {
            const float* xgb = xg + ((size_t)t * BB + bown) * NGATE;
            const float* p0 = g_part + (size_t)bown * NGATE;
            const float* p1 = p0 + 1 * (size_t)(BB * NGATE);
            const float* p2 = p0 + 2 * (size_t)(BB * NGATE);
            const float* p3 = p0 + 3 * (size_t)(BB * NGATE);

            float gv[4][2];
#pragma unroll
            for (int gi = 0; gi < 4; gi++) {
                int n = (gi << 10) | hc2;
                float2 v  = *(const float2*)(xgb + n);
                float2 q0 = *(const float2*)(p0 + n);
                float2 q1 = *(const float2*)(p1 + n);
                float2 q2 = *(const float2*)(p2 + n);
                float2 q3 = *(const float2*)(p3 + n);
                gv[gi][0] = v.x + q0.x + q1.x + q2.x + q3.x;
                gv[gi][1] = v.y + q0.y + q1.y + q2.y + q3.y;
            }
            gv[0][0] += bb0.x; gv[0][1] += bb0.y;
            gv[1][0] += bb1.x; gv[1][1] += bb1.y;
            gv[2][0] += bb2.x; gv[2][1] += bb2.y;
            gv[3][0] += bb3.x; gv[3][1] += bb3.y;

            float hv[2];
            float* cr = (float*)&creg;
#pragma unroll
            for (int e = 0; e < 2; e++) {
                float ig = 1.f / (1.f + expf(-gv[0][e]));
                float fg = 1.f / (1.f + expf(-gv[1][e]));
                float og = 1.f / (1.f + expf(-gv[2][e]));
                float ug = tanhf(gv[3][e]);
                float c = fg * cr[e] + ig * ug;
                cr[e] = c;
                hv[e] = og * tanhf(c);
            }
            float2 hvec = make_float2(hv[0], hv[1]);
            if (t == TT - 1)
                *(float2*)(out + bown * HH + hc2) = hvec;
            else
                *(float2*)(g_h + bown * HH + hc2) = hvec;
        }

        grid_barrier();   // h visible before next GEMM
    }
}

// ---------------------------------------------------------------------------
// Launch. Inputs: x[128,512,1024], adjacency (unused), Wx[4,1024,1024],
// Wh[4,1024,1024], b[4,1024]. Output: h [128,1024] f32. Graph: 2 nodes.
// ---------------------------------------------------------------------------
extern "C" void kernel_launch(void* const* d_in, const int* in_sizes, int n_in,
                              void* d_out, int out_size)
{
    const float* x    = (const float*)d_in[0];
    const float* Wx   = (const float*)d_in[2];
    const float* Wh   = (const float*)d_in[3];
    const float* bias = (const float*)d_in[4];
    float* out = (float*)d_out;

    float* xg;
    cudaGetSymbolAddress((void**)&xg, g_xg);

    const int xg_smem  = (3 * XGA + 3 * XGB) * 4;           // 107520 B
    const int rec_smem = (256 * LDB + 3 * RCA) * 4;         // 194560 B
    static int configured = 0;
    if (!configured) {
        cudaFuncSetAttribute(gemm_xgates,
                             cudaFuncAttributeMaxDynamicSharedMemorySize, xg_smem);
        cudaFuncSetAttribute(lstm_recurrence,
                             cudaFuncAttributeMaxDynamicSharedMemorySize, rec_smem);
        configured = 1;
    }

    gemm_xgates<<<dim3(32, 512), 512, xg_smem>>>(x, Wx, xg);
    lstm_recurrence<<<NCTA, 512, rec_smem>>>(Wh, xg, bias, out);
}

// round 11
// speedup vs baseline: 1.2674x; 1.0588x over previous
#include <cuda_runtime.h>
#include <math.h>
#include <stdint.h>

#define BB 128
#define TT 512
#define DD 1024
#define HH 1024
#define NGATE 4096   // 4*H
#define NCTA 128     // persistent grid size (1/SM, all co-resident)
#define NSPLIT 8     // k-splits in recurrence

#define LDN 264      // B smem row stride (256n + 8 pad): 264 % 32 == 8 -> conflict-free
#define LDAK 36      // A smem row stride ([m][k32+4]): 36 % 32 == 4 -> conflict-free

// Scratch (static device globals — no runtime allocation).
__device__ float    g_xg[(size_t)TT * BB * NGATE];     // [t][b][4H] input projections (f32)
__device__ float    g_part[NSPLIT * BB * NGATE];       // split-K partials (f32)
__device__ uint32_t g_h[BB * HH];                      // recurrent h (tf32 bits)
__device__ uint32_t g_xtf[(size_t)BB * TT * DD];       // x pre-converted to tf32 bits
__device__ uint32_t g_wxtf[4 * DD * HH];               // Wx tf32 bits
__device__ uint32_t g_whtf[4 * HH * HH];               // Wh tf32 bits
__device__ unsigned g_bar;                             // grid barrier counter (never reset)

__device__ __forceinline__ uint32_t f2tf32(float f)
{
    uint32_t u;
    asm("cvt.rna.tf32.f32 %0, %1;" : "=r"(u) : "f"(f));
    return u;
}

__device__ __forceinline__ void mma_tf32(float* d, const uint32_t* a, const uint32_t* b)
{
    asm volatile(
        "mma.sync.aligned.m16n8k8.row.col.f32.tf32.tf32.f32 "
        "{%0,%1,%2,%3},{%4,%5,%6,%7},{%8,%9},{%0,%1,%2,%3};"
        : "+f"(d[0]), "+f"(d[1]), "+f"(d[2]), "+f"(d[3])
        : "r"(a[0]), "r"(a[1]), "r"(a[2]), "r"(a[3]), "r"(b[0]), "r"(b[1]));
}

__device__ __forceinline__ void cpa16(uint32_t dst_smem, const void* src)
{
    asm volatile("cp.async.cg.shared.global [%0], [%1], 16;"
                 :: "r"(dst_smem), "l"(src));
}
__device__ __forceinline__ void cpa_commit()
{
    asm volatile("cp.async.commit_group;");
}
template <int N> __device__ __forceinline__ void cpa_wait()
{
    asm volatile("cp.async.wait_group %0;" :: "n"(N));
}

extern __shared__ uint32_t dynu[];

// ---------------------------------------------------------------------------
// Pre-convert: f32 -> tf32 bits, elementwise (float4 granularity).
// ---------------------------------------------------------------------------
__global__ __launch_bounds__(256) void cvt_tf32_arr(
    const float4* __restrict__ src, uint4* __restrict__ dst, int n4)
{
    int i = blockIdx.x * blockDim.x + threadIdx.x;
    if (i < n4) {
        float4 v = src[i];
        uint4 u;
        u.x = f2tf32(v.x); u.y = f2tf32(v.y);
        u.z = f2tf32(v.z); u.w = f2tf32(v.w);
        dst[i] = u;
    }
}

// ---------------------------------------------------------------------------
// GEMM1 (tf32): xg[t][b][n] = sum_k x[b][t][k] * Wx[g][k][h]
// Sources pre-converted (no cvt in loop). Block 128m x 256n x 32k, 512 thr,
// warp grid 4m x 4n, warp tile 32x64. 3-stage cp.async pipeline.
// grid = (16 n-tiles, 512 t).
// ---------------------------------------------------------------------------
#define XGA (128 * LDAK)        // words per A stage
#define XGB (32 * LDN)          // words per B stage

__global__ __launch_bounds__(512, 1) void gemm_xgates(float* __restrict__ out)
{
    uint32_t* Sa = dynu;                 // [3][128][LDAK]
    uint32_t* Sb = dynu + 3 * XGA;       // [3][32][LDN]
    const uint32_t sa_base = (uint32_t)__cvta_generic_to_shared(Sa);
    const uint32_t sb_base = (uint32_t)__cvta_generic_to_shared(Sb);

    const int tid  = threadIdx.x;
    const int lane = tid & 31;
    const int wid  = tid >> 5;        // 0..15
    const int gq   = lane >> 2;
    const int cq   = lane & 3;

    const int t  = blockIdx.y;
    const int n0 = blockIdx.x * 256;
    const int gg = n0 >> 10;
    const int hb = n0 & 1023;

    const int m0w = (wid >> 2) * 32;  // 4 warps along m
    const int n0w = (wid & 3) * 64;   // 4 warps along n (tile 64)

    float acc[2][8][4];
#pragma unroll
    for (int i = 0; i < 2; i++)
#pragma unroll
        for (int j = 0; j < 8; j++)
#pragma unroll
            for (int e = 0; e < 4; e++) acc[i][j][e] = 0.f;

    const uint32_t* Wg = g_wxtf + (size_t)gg * DD * HH + hb;

    // A copy: row am = tid>>2 (0..127), segs (tid&3)*2 + j (8 x 16B per row)
    const int am  = tid >> 2;
    const int as0 = (tid & 3) * 2;
    const uint32_t* axsrc = g_xtf + (size_t)am * (TT * DD) + (size_t)t * DD + as0 * 4;
    // B copy: row bk = tid>>4 (0..31), segs (tid&15)*4 + j (64 x 16B per row)
    const int bk  = tid >> 4;
    const int bs0 = (tid & 15) * 4;

    auto copy_stage = [&](int kt) {
        int s = kt % 3;
        uint32_t da = sa_base + (uint32_t)(s * XGA + am * LDAK + as0 * 4) * 4;
        const uint32_t* srca = axsrc + kt * 32;
#pragma unroll
        for (int j = 0; j < 2; j++)
            cpa16(da + j * 16, srca + j * 4);
        uint32_t db = sb_base + (uint32_t)(s * XGB + bk * LDN + bs0 * 4) * 4;
        const uint32_t* srcb = Wg + (size_t)(kt * 32 + bk) * HH + bs0 * 4;
#pragma unroll
        for (int j = 0; j < 4; j++)
            cpa16(db + j * 16, srcb + j * 4);
        cpa_commit();
    };

    copy_stage(0);
    copy_stage(1);

    for (int kt = 0; kt < 32; kt++) {
        if (kt == 31) cpa_wait<0>(); else cpa_wait<1>();
        __syncthreads();
        if (kt + 2 < 32) copy_stage(kt + 2);

        const uint32_t* Af = Sa + (kt % 3) * XGA;
        const uint32_t* Bf = Sb + (kt % 3) * XGB;
#pragma unroll
        for (int kk = 0; kk < 4; kk++) {
            const int kb = kk * 8;
            uint32_t af[2][4], bf[8][2];
#pragma unroll
            for (int mt = 0; mt < 2; mt++) {
                int m = m0w + mt * 16 + gq;
                af[mt][0] = Af[m * LDAK + kb + cq];
                af[mt][1] = Af[(m + 8) * LDAK + kb + cq];
                af[mt][2] = Af[m * LDAK + kb + cq + 4];
                af[mt][3] = Af[(m + 8) * LDAK + kb + cq + 4];
            }
#pragma unroll
            for (int nt = 0; nt < 8; nt++) {
                int n = n0w + nt * 8 + gq;
                bf[nt][0] = Bf[(kb + cq) * LDN + n];
                bf[nt][1] = Bf[(kb + cq + 4) * LDN + n];
            }
#pragma unroll
            for (int mt = 0; mt < 2; mt++)
#pragma unroll
                for (int nt = 0; nt < 8; nt++)
                    mma_tf32(acc[mt][nt], af[mt], bf[nt]);
        }
    }

#pragma unroll
    for (int mt = 0; mt < 2; mt++) {
        int r0 = m0w + mt * 16 + gq;
#pragma unroll
        for (int nt = 0; nt < 8; nt++) {
            int cc = n0 + n0w + nt * 8 + 2 * cq;
            float* p0 = out + ((size_t)t * BB + r0) * NGATE + cc;
            float* p1 = out + ((size_t)t * BB + r0 + 8) * NGATE + cc;
            *(float2*)p0 = make_float2(acc[mt][nt][0], acc[mt][nt][1]);
            *(float2*)p1 = make_float2(acc[mt][nt][2], acc[mt][nt][3]);
        }
    }
}

// ---------------------------------------------------------------------------
// Grid barrier: stateless generation counter; volatile poll + nanosleep.
// ---------------------------------------------------------------------------
__device__ __forceinline__ void grid_barrier()
{
    __syncthreads();
    if (threadIdx.x == 0) {
        __threadfence();
        unsigned old = atomicAdd(&g_bar, 1u);
        unsigned target = (old / NCTA + 1u) * (unsigned)NCTA;
        while (*(volatile unsigned*)&g_bar < target) { __nanosleep(32); }
        __threadfence();
    }
    __syncthreads();
}

// ---------------------------------------------------------------------------
// Persistent recurrence (tf32): 128 CTAs x 512 threads, 512 steps.
// CTA = (n-tile 0..15 width 256, k-split 0..7 width 128). Wh slice
// (128k x 256n tf32 bits, stride 264) persistent in smem; h (tf32 bits,
// written by activation) streamed per step in 4 chunks of k32 via 3-stage
// cp.async ring. Warp grid 4m x 4n, warp tile 32x64. No cvt in inner loop.
// ---------------------------------------------------------------------------
#define RCA (128 * LDAK)   // words per A ring stage

__global__ __launch_bounds__(512, 1) void lstm_recurrence(
    const float* __restrict__ xg, const float* __restrict__ bias,
    float* __restrict__ out)
{
    uint32_t* BsW   = dynu;                 // [128][LDN] persistent Wh slice
    uint32_t* Aring = dynu + 128 * LDN;     // [3][128][LDAK] h chunks (bits)
    const uint32_t ar_base = (uint32_t)__cvta_generic_to_shared(Aring);

    const int tid  = threadIdx.x;
    const int lane = tid & 31;
    const int wid  = tid >> 5;
    const int gq   = lane >> 2;
    const int cq   = lane & 3;

    const int nt = blockIdx.x & 15;     // n-tile (width 256)
    const int ks = blockIdx.x >> 4;     // k-split 0..7 (width 128)
    const int n0 = nt * 256;
    const int gg = n0 >> 10;
    const int hb = n0 & 1023;
    const int k0 = ks * 128;

    const int m0w = (wid >> 2) * 32;
    const int n0w = (wid & 3) * 64;

    const uint32_t* Wg = g_whtf + (size_t)gg * HH * HH + hb;

    // ---- preload Wh slice -> BsW[k][n] (pre-converted bits), once ----
    for (int i = tid; i < 128 * 64; i += 512) {   // uint4 granules: 128k x 64
        int kr = i >> 6;
        int nc = (i & 63) * 4;
        uint4 v = *(const uint4*)(Wg + (size_t)(k0 + kr) * HH + nc);
        *(uint4*)&BsW[kr * LDN + nc] = v;
    }

    // Activation role: batch row b = blockIdx.x, cols tid*2..+1
    const int bown = blockIdx.x;
    const int hc2  = tid * 2;
    float2 creg = make_float2(0.f, 0.f);
    float2 bb0 = *(const float2*)(bias + hc2);
    float2 bb1 = *(const float2*)(bias + 1024 + hc2);
    float2 bb2 = *(const float2*)(bias + 2048 + hc2);
    float2 bb3 = *(const float2*)(bias + 3072 + hc2);

    *(uint2*)(g_h + bown * HH + hc2) = make_uint2(0u, 0u);
    grid_barrier();

    // A copy: row am = tid>>2, segs (tid&3)*2 + j (8 x 16B per row)
    const int am  = tid >> 2;
    const int as0 = (tid & 3) * 2;
    const uint32_t* hsrc = g_h + (size_t)am * HH + k0 + as0 * 4;

    for (int t = 0; t < TT; t++) {
        float acc[2][8][4];
#pragma unroll
        for (int i = 0; i < 2; i++)
#pragma unroll
            for (int j = 0; j < 8; j++)
#pragma unroll
                for (int e = 0; e < 4; e++) acc[i][j][e] = 0.f;

        auto copy_chunk = [&](int c) {
            uint32_t da = ar_base + (uint32_t)((c % 3) * RCA + am * LDAK + as0 * 4) * 4;
            const uint32_t* src = hsrc + c * 32;
#pragma unroll
            for (int j = 0; j < 2; j++)
                cpa16(da + j * 16, src + j * 4);
            cpa_commit();
        };

        copy_chunk(0);
        copy_chunk(1);

#pragma unroll
        for (int c = 0; c < 4; c++) {
            if (c == 3) cpa_wait<0>(); else cpa_wait<1>();
            __syncthreads();
            if (c + 2 < 4) copy_chunk(c + 2);

            const uint32_t* Af = Aring + (c % 3) * RCA;
#pragma unroll
            for (int kk = 0; kk < 4; kk++) {
                const int kb = kk * 8;
                const int kw = c * 32 + kb;
                uint32_t af[2][4], bf[8][2];
#pragma unroll
                for (int mt = 0; mt < 2; mt++) {
                    int m = m0w + mt * 16 + gq;
                    af[mt][0] = Af[m * LDAK + kb + cq];
                    af[mt][1] = Af[(m + 8) * LDAK + kb + cq];
                    af[mt][2] = Af[m * LDAK + kb + cq + 4];
                    af[mt][3] = Af[(m + 8) * LDAK + kb + cq + 4];
                }
#pragma unroll
                for (int nt2 = 0; nt2 < 8; nt2++) {
                    int n = n0w + nt2 * 8 + gq;
                    bf[nt2][0] = BsW[(kw + cq) * LDN + n];
                    bf[nt2][1] = BsW[(kw + cq + 4) * LDN + n];
                }
#pragma unroll
                for (int mt = 0; mt < 2; mt++)
#pragma unroll
                    for (int nt2 = 0; nt2 < 8; nt2++)
                        mma_tf32(acc[mt][nt2], af[mt], bf[nt2]);
            }
        }

        // store partials
        float* pbase = g_part + (size_t)ks * (BB * NGATE);
#pragma unroll
        for (int mt = 0; mt < 2; mt++) {
            int r0 = m0w + mt * 16 + gq;
#pragma unroll
            for (int nt2 = 0; nt2 < 8; nt2++) {
                int cc = n0 + n0w + nt2 * 8 + 2 * cq;
                *(float2*)(pbase + (size_t)r0 * NGATE + cc) =
                    make_float2(acc[mt][nt2][0], acc[mt][nt2][1]);
                *(float2*)(pbase + (size_t)(r0 + 8) * NGATE + cc) =
                    make_float2(acc[mt][nt2][2], acc[mt][nt2][3]);
            }
        }

        grid_barrier();   // partials visible

        // ---- fused activation: gates = xg + bias + sum of 8 partials ----
        {
            const float* xgb = xg + ((size_t)t * BB + bown) * NGATE;
            const float* pb  = g_part + (size_t)bown * NGATE;

            float gv[4][2];
#pragma unroll
            for (int gi = 0; gi < 4; gi++) {
                int n = (gi << 10) | hc2;
                float2 v = *(const float2*)(xgb + n);
                float sx = v.x, sy = v.y;
#pragma unroll
                for (int s = 0; s < NSPLIT; s++) {
                    float2 q = *(const float2*)(pb + (size_t)s * (BB * NGATE) + n);
                    sx += q.x; sy += q.y;
                }
                gv[gi][0] = sx; gv[gi][1] = sy;
            }
            gv[0][0] += bb0.x; gv[0][1] += bb0.y;
            gv[1][0] += bb1.x; gv[1][1] += bb1.y;
            gv[2][0] += bb2.x; gv[2][1] += bb2.y;
            gv[3][0] += bb3.x; gv[3][1] += bb3.y;

            float hv[2];
            float* cr = (float*)&creg;
#pragma unroll
            for (int e = 0; e < 2; e++) {
                float ig = 1.f / (1.f + expf(-gv[0][e]));
                float fg = 1.f / (1.f + expf(-gv[1][e]));
                float og = 1.f / (1.f + expf(-gv[2][e]));
                float ug = tanhf(gv[3][e]);
                float c = fg * cr[e] + ig * ug;
                cr[e] = c;
                hv[e] = og * tanhf(c);
            }
            if (t == TT - 1) {
                *(float2*)(out + bown * HH + hc2) = make_float2(hv[0], hv[1]);
            } else {
                *(uint2*)(g_h + bown * HH + hc2) =
                    make_uint2(f2tf32(hv[0]), f2tf32(hv[1]));
            }
        }

        grid_barrier();   // h visible before next GEMM
    }
}

// ---------------------------------------------------------------------------
// Launch. Inputs: x[128,512,1024], adjacency (unused), Wx[4,1024,1024],
// Wh[4,1024,1024], b[4,1024]. Output: h [128,1024] f32. Graph: 5 nodes.
// ---------------------------------------------------------------------------
extern "C" void kernel_launch(void* const* d_in, const int* in_sizes, int n_in,
                              void* d_out, int out_size)
{
    const float* x    = (const float*)d_in[0];
    const float* Wx   = (const float*)d_in[2];
    const float* Wh   = (const float*)d_in[3];
    const float* bias = (const float*)d_in[4];
    float* out = (float*)d_out;

    float *xg;
    uint32_t *xtf, *wxtf, *whtf;
    cudaGetSymbolAddress((void**)&xg,   g_xg);
    cudaGetSymbolAddress((void**)&xtf,  g_xtf);
    cudaGetSymbolAddress((void**)&wxtf, g_wxtf);
    cudaGetSymbolAddress((void**)&whtf, g_whtf);

    const int xg_smem  = (3 * XGA + 3 * XGB) * 4;           // 156672 B
    const int rec_smem = (128 * LDN + 3 * RCA) * 4;         // 190464 B
    static int configured = 0;
    if (!configured) {
        cudaFuncSetAttribute(gemm_xgates,
                             cudaFuncAttributeMaxDynamicSharedMemorySize, xg_smem);
        cudaFuncSetAttribute(lstm_recurrence,
                             cudaFuncAttributeMaxDynamicSharedMemorySize, rec_smem);
        configured = 1;
    }

    const int nx4 = BB * TT * DD / 4;      // 16M float4
    const int nw4 = 4 * DD * HH / 4;       // 1M float4
    cvt_tf32_arr<<<(nx4 + 255) / 256, 256>>>((const float4*)x,  (uint4*)xtf,  nx4);
    cvt_tf32_arr<<<(nw4 + 255) / 256, 256>>>((const float4*)Wx, (uint4*)wxtf, nw4);
    cvt_tf32_arr<<<(nw4 + 255) / 256, 256>>>((const float4*)Wh, (uint4*)whtf, nw4);

    gemm_xgates<<<dim3(16, 512), 512, xg_smem>>>(xg);
    lstm_recurrence<<<NCTA, 512, rec_smem>>>(xg, bias, out);
}